// round 3
// baseline (speedup 1.0000x reference)
#include <cuda_runtime.h>
#include <math.h>

// DistinctionLoss fused single-kernel version (hardened: 1 block/SM residency).
// features [8,4096,256] f32, scores [8,4096,1] f32 -> scalar f32.
//
// mean(gram) = sum_b ||s_b||^2 / (B*N^2), s_b = sum_n unit(features[b,n,:]).
// One persistent kernel: phase1 (norms + s_b accum) -> grid barrier ->
// phase2 (per-row dot, BCE) -> grid barrier -> block 0 finalizes + resets state.

#define BB 8
#define NN 4096
#define DD 256
#define NBLK 128
#define NTHREADS 512
#define NWARPS (NTHREADS / 32)                 // 16
#define ROWS_PER_BLOCK ((BB * NN) / NBLK)      // 256
#define ROWS_PER_WARP  (ROWS_PER_BLOCK / NWARPS) // 16

// Persistent scratch; zero-initialized at module load, self-reset each launch.
__device__ float  g_s[BB * DD];
__device__ double g_bce;
__device__ unsigned int g_count;
__device__ volatile unsigned int g_gen;

__device__ __forceinline__ void grid_barrier() {
    __syncthreads();
    if (threadIdx.x == 0) {
        __threadfence();                    // publish this block's writes
        unsigned int gen = g_gen;           // read phase BEFORE arriving
        if (atomicAdd(&g_count, 1u) == NBLK - 1) {
            g_count = 0;
            __threadfence();
            g_gen = gen + 1;                // release
        } else {
            while (g_gen == gen) __nanosleep(32);
        }
    }
    __syncthreads();
}

__global__ void __launch_bounds__(NTHREADS, 1) fused_kernel(
        const float* __restrict__ feat,
        const float* __restrict__ scores,
        float* __restrict__ out) {
    __shared__ float s_acc[DD];
    __shared__ float s_vec[DD];
    __shared__ float s_red[NWARPS];
    __shared__ float s_fin[NTHREADS];

    int tid  = threadIdx.x;
    int wid  = tid >> 5;
    int lane = tid & 31;

    int rowBase = blockIdx.x * ROWS_PER_BLOCK;   // 256 | 4096 -> single batch
    int b       = rowBase / NN;
    int row0    = rowBase + wid * ROWS_PER_WARP;

    if (tid < DD) s_acc[tid] = 0.0f;
    __syncthreads();

    // ---------------- Phase 1: row norms + s_b accumulation ----------------
    float rn[ROWS_PER_WARP];
    float acc[8] = {0.f,0.f,0.f,0.f,0.f,0.f,0.f,0.f};

    #pragma unroll
    for (int r = 0; r < ROWS_PER_WARP; r++) {
        int row = row0 + r;
        const float4* p = (const float4*)(feat + (size_t)row * DD);
        float4 v0 = p[lane];
        float4 v1 = p[lane + 32];
        float ss = v0.x*v0.x + v0.y*v0.y + v0.z*v0.z + v0.w*v0.w
                 + v1.x*v1.x + v1.y*v1.y + v1.z*v1.z + v1.w*v1.w;
        #pragma unroll
        for (int o = 16; o > 0; o >>= 1)
            ss += __shfl_xor_sync(0xffffffffu, ss, o);
        float r_n = rsqrtf(fmaxf(ss, 1e-24f));
        rn[r] = r_n;                               // kept in regs for phase 2
        acc[0] += v0.x * r_n; acc[1] += v0.y * r_n;
        acc[2] += v0.z * r_n; acc[3] += v0.w * r_n;
        acc[4] += v1.x * r_n; acc[5] += v1.y * r_n;
        acc[6] += v1.z * r_n; acc[7] += v1.w * r_n;
    }

    int d0 = lane * 4;
    atomicAdd(&s_acc[d0 + 0],       acc[0]);
    atomicAdd(&s_acc[d0 + 1],       acc[1]);
    atomicAdd(&s_acc[d0 + 2],       acc[2]);
    atomicAdd(&s_acc[d0 + 3],       acc[3]);
    atomicAdd(&s_acc[128 + d0 + 0], acc[4]);
    atomicAdd(&s_acc[128 + d0 + 1], acc[5]);
    atomicAdd(&s_acc[128 + d0 + 2], acc[6]);
    atomicAdd(&s_acc[128 + d0 + 3], acc[7]);
    __syncthreads();

    if (tid < DD) atomicAdd(&g_s[b * DD + tid], s_acc[tid]);

    grid_barrier();

    // ---------------- Phase 2: per-row dot with s_b -> BCE ----------------
    if (tid < DD) s_vec[tid] = __ldcg(&g_s[b * DD + tid]); // L2 (atomics landed there)
    __syncthreads();

    const float4* sv = (const float4*)s_vec;
    float4 s0 = sv[lane];
    float4 s1 = sv[lane + 32];

    float local = 0.0f;
    #pragma unroll
    for (int r = 0; r < ROWS_PER_WARP; r++) {
        int row = row0 + r;
        const float4* p = (const float4*)(feat + (size_t)row * DD);
        float4 v0 = p[lane];
        float4 v1 = p[lane + 32];
        float dot = v0.x*s0.x + v0.y*s0.y + v0.z*s0.z + v0.w*s0.w
                  + v1.x*s1.x + v1.y*s1.y + v1.z*s1.z + v1.w*s1.w;
        #pragma unroll
        for (int o = 16; o > 0; o >>= 1)
            dot += __shfl_xor_sync(0xffffffffu, dot, o);
        if (lane == 0) {
            float fs  = dot * rn[r];                       // unit-row . s_b
            float sim = (fs - 1.0f) * (1.0f / (float)(NN - 1));
            float t   = 1.0f - fmaxf(sim, 0.0f);
            float sc  = scores[row];
            float ls  = fmaxf(logf(sc),    -100.0f);
            float l1  = fmaxf(log1pf(-sc), -100.0f);
            local += -(t * ls + (1.0f - t) * l1);
        }
    }

    if (lane == 0) s_red[wid] = local;
    __syncthreads();
    if (tid == 0) {
        float sum = 0.0f;
        #pragma unroll
        for (int i = 0; i < NWARPS; i++) sum += s_red[i];
        atomicAdd(&g_bce, (double)sum);
    }

    grid_barrier();

    // ---------------- Finalize + reset (block 0 only) ----------------
    if (blockIdx.x == 0) {
        float ss = 0.0f;
        #pragma unroll
        for (int i = 0; i < (BB * DD) / NTHREADS; i++) {
            float v = __ldcg(&g_s[tid + i * NTHREADS]);
            ss += v * v;
        }
        s_fin[tid] = ss;
        __syncthreads();
        #pragma unroll
        for (int o = NTHREADS / 2; o > 0; o >>= 1) {
            if (tid < o) s_fin[tid] += s_fin[tid + o];
            __syncthreads();
        }
        if (tid == 0) {
            double bce       = atomicAdd(&g_bce, 0.0) / (double)(BB * NN);
            double mean_gram = (double)s_fin[0] /
                               ((double)BB * (double)NN * (double)NN);
            out[0] = (float)(bce + (1.0 - mean_gram));
            g_bce = 0.0;                                   // reset for next launch
        }
        __syncthreads();                                   // all reads of g_s done
        #pragma unroll
        for (int i = 0; i < (BB * DD) / NTHREADS; i++)
            g_s[tid + i * NTHREADS] = 0.0f;                // reset for next launch
    }
}

extern "C" void kernel_launch(void* const* d_in, const int* in_sizes, int n_in,
                              void* d_out, int out_size) {
    const float* feat   = (const float*)d_in[0];
    const float* scores = (const float*)d_in[1];
    float* out = (float*)d_out;

    fused_kernel<<<NBLK, NTHREADS>>>(feat, scores, out);
}

// round 5
// speedup vs baseline: 1.1235x; 1.1235x over previous
#include <cuda_runtime.h>
#include <math.h>

// DistinctionLoss fused single-kernel, MLP-batched version.
// features [8,4096,256] f32, scores [8,4096,1] f32 -> scalar f32.
//
// mean(gram) = sum_b ||s_b||^2 / (B*N^2), s_b = sum_n unit(features[b,n,:]).
// One persistent kernel: phase1 (norms + s_b accum) -> grid barrier ->
// phase2 (per-row dot vs s_b, BCE) -> grid barrier -> block 0 finalize+reset.
// Rows processed 4 at a time: 8 LDG.128 in flight per warp, 4 interleaved
// shuffle-reduction chains to hide SHFL latency.

#define BB 8
#define NN 4096
#define DD 256
#define NBLK 128
#define NTHREADS 512
#define NWARPS (NTHREADS / 32)                   // 16
#define ROWS_PER_BLOCK ((BB * NN) / NBLK)        // 256
#define ROWS_PER_WARP  (ROWS_PER_BLOCK / NWARPS) // 16
#define RBATCH 4

// Persistent scratch; zero-initialized at module load, self-reset each launch.
__device__ float  g_s[BB * DD];
__device__ double g_bce;
__device__ unsigned int g_count;
__device__ volatile unsigned int g_gen;

__device__ __forceinline__ void grid_barrier() {
    __syncthreads();
    if (threadIdx.x == 0) {
        __threadfence();                    // publish this block's writes
        unsigned int gen = g_gen;           // read phase BEFORE arriving
        if (atomicAdd(&g_count, 1u) == NBLK - 1) {
            g_count = 0;
            __threadfence();
            g_gen = gen + 1;                // release
        } else {
            while (g_gen == gen) __nanosleep(32);
        }
    }
    __syncthreads();
}

__global__ void __launch_bounds__(NTHREADS, 1) fused_kernel(
        const float* __restrict__ feat,
        const float* __restrict__ scores,
        float* __restrict__ out) {
    __shared__ float s_acc[DD];
    __shared__ float s_vec[DD];
    __shared__ float s_rn[ROWS_PER_BLOCK];
    __shared__ float s_red[NWARPS];
    __shared__ float s_fin[NTHREADS];

    int tid  = threadIdx.x;
    int wid  = tid >> 5;
    int lane = tid & 31;

    int rowBase = blockIdx.x * ROWS_PER_BLOCK;   // 256 | 4096 -> single batch
    int b       = rowBase / NN;
    int row0    = rowBase + wid * ROWS_PER_WARP;

    if (tid < DD) s_acc[tid] = 0.0f;
    __syncthreads();

    // ---------------- Phase 1: row norms + s_b accumulation ----------------
    float4 acc0 = make_float4(0.f, 0.f, 0.f, 0.f);
    float4 acc1 = make_float4(0.f, 0.f, 0.f, 0.f);

    #pragma unroll
    for (int rb = 0; rb < ROWS_PER_WARP; rb += RBATCH) {
        float4 a0[RBATCH], a1[RBATCH];
        #pragma unroll
        for (int r = 0; r < RBATCH; r++) {        // 8 independent LDG.128
            const float4* p = (const float4*)(feat + (size_t)(row0 + rb + r) * DD);
            a0[r] = p[lane];
            a1[r] = p[lane + 32];
        }
        float ss[RBATCH];
        #pragma unroll
        for (int r = 0; r < RBATCH; r++)
            ss[r] = a0[r].x*a0[r].x + a0[r].y*a0[r].y + a0[r].z*a0[r].z + a0[r].w*a0[r].w
                  + a1[r].x*a1[r].x + a1[r].y*a1[r].y + a1[r].z*a1[r].z + a1[r].w*a1[r].w;
        #pragma unroll
        for (int o = 16; o > 0; o >>= 1) {        // 4 interleaved butterflies
            #pragma unroll
            for (int r = 0; r < RBATCH; r++)
                ss[r] += __shfl_xor_sync(0xffffffffu, ss[r], o);
        }
        #pragma unroll
        for (int r = 0; r < RBATCH; r++) {
            float rn_ = rsqrtf(fmaxf(ss[r], 1e-24f));
            if (lane == 0) s_rn[wid * ROWS_PER_WARP + rb + r] = rn_;
            acc0.x += a0[r].x * rn_; acc0.y += a0[r].y * rn_;
            acc0.z += a0[r].z * rn_; acc0.w += a0[r].w * rn_;
            acc1.x += a1[r].x * rn_; acc1.y += a1[r].y * rn_;
            acc1.z += a1[r].z * rn_; acc1.w += a1[r].w * rn_;
        }
    }

    int d0 = lane * 4;
    atomicAdd(&s_acc[d0 + 0],       acc0.x);
    atomicAdd(&s_acc[d0 + 1],       acc0.y);
    atomicAdd(&s_acc[d0 + 2],       acc0.z);
    atomicAdd(&s_acc[d0 + 3],       acc0.w);
    atomicAdd(&s_acc[128 + d0 + 0], acc1.x);
    atomicAdd(&s_acc[128 + d0 + 1], acc1.y);
    atomicAdd(&s_acc[128 + d0 + 2], acc1.z);
    atomicAdd(&s_acc[128 + d0 + 3], acc1.w);
    __syncthreads();

    if (tid < DD) atomicAdd(&g_s[b * DD + tid], s_acc[tid]);

    grid_barrier();

    // ---------------- Phase 2: per-row dot with s_b -> BCE ----------------
    if (tid < DD) s_vec[tid] = __ldcg(&g_s[b * DD + tid]); // atomics landed in L2
    __syncthreads();

    const float4* sv = (const float4*)s_vec;
    float4 s0 = sv[lane];
    float4 s1 = sv[lane + 32];

    float local = 0.0f;
    #pragma unroll
    for (int rb = 0; rb < ROWS_PER_WARP; rb += RBATCH) {
        float4 a0[RBATCH], a1[RBATCH];
        #pragma unroll
        for (int r = 0; r < RBATCH; r++) {
            const float4* p = (const float4*)(feat + (size_t)(row0 + rb + r) * DD);
            a0[r] = p[lane];
            a1[r] = p[lane + 32];
        }
        float dt[RBATCH];
        #pragma unroll
        for (int r = 0; r < RBATCH; r++)
            dt[r] = a0[r].x*s0.x + a0[r].y*s0.y + a0[r].z*s0.z + a0[r].w*s0.w
                  + a1[r].x*s1.x + a1[r].y*s1.y + a1[r].z*s1.z + a1[r].w*s1.w;
        #pragma unroll
        for (int o = 16; o > 0; o >>= 1) {
            #pragma unroll
            for (int r = 0; r < RBATCH; r++)
                dt[r] += __shfl_xor_sync(0xffffffffu, dt[r], o);
        }
        if (lane == 0) {
            #pragma unroll
            for (int r = 0; r < RBATCH; r++) {
                int row = row0 + rb + r;
                float fs  = dt[r] * s_rn[wid * ROWS_PER_WARP + rb + r];
                float sim = (fs - 1.0f) * (1.0f / (float)(NN - 1));
                float t   = 1.0f - fmaxf(sim, 0.0f);
                float sc  = scores[row];
                float ls  = fmaxf(logf(sc),    -100.0f);
                float l1  = fmaxf(log1pf(-sc), -100.0f);
                local += -(t * ls + (1.0f - t) * l1);
            }
        }
    }

    if (lane == 0) s_red[wid] = local;
    __syncthreads();
    if (tid == 0) {
        float sum = 0.0f;
        #pragma unroll
        for (int i = 0; i < NWARPS; i++) sum += s_red[i];
        atomicAdd(&g_bce, (double)sum);
    }

    grid_barrier();

    // ---------------- Finalize + reset (block 0 only) ----------------
    if (blockIdx.x == 0) {
        float ss = 0.0f;
        #pragma unroll
        for (int i = 0; i < (BB * DD) / NTHREADS; i++) {
            float v = __ldcg(&g_s[tid + i * NTHREADS]);
            ss += v * v;
        }
        s_fin[tid] = ss;
        __syncthreads();
        #pragma unroll
        for (int o = NTHREADS / 2; o > 0; o >>= 1) {
            if (tid < o) s_fin[tid] += s_fin[tid + o];
            __syncthreads();
        }
        if (tid == 0) {
            double bce       = atomicAdd(&g_bce, 0.0) / (double)(BB * NN);
            double mean_gram = (double)s_fin[0] /
                               ((double)BB * (double)NN * (double)NN);
            out[0] = (float)(bce + (1.0 - mean_gram));
            g_bce = 0.0;                                   // reset for next launch
        }
        __syncthreads();                                   // all reads of g_s done
        #pragma unroll
        for (int i = 0; i < (BB * DD) / NTHREADS; i++)
            g_s[tid + i * NTHREADS] = 0.0f;                // reset for next launch
    }
}

extern "C" void kernel_launch(void* const* d_in, const int* in_sizes, int n_in,
                              void* d_out, int out_size) {
    const float* feat   = (const float*)d_in[0];
    const float* scores = (const float*)d_in[1];
    float* out = (float*)d_out;

    fused_kernel<<<NBLK, NTHREADS>>>(feat, scores, out);
}